// round 4
// baseline (speedup 1.0000x reference)
#include <cuda_runtime.h>

#define NB 64
#define NT 2048
#define ND 512
#define NU 10
#define CHUNKS 8
#define CROWS (NT / CHUNKS)       // 256 rows per chunk
#define A_WARPS 8
#define A_THREADS 256
#define ROWS_PER_WARP (CROWS / A_WARPS)   // 32

// Scratch (device globals; no runtime allocation)
__device__ float g_scores[NB * NT];            // raw pre-softmax scores (512 KB)
__device__ float g_pm[NB * CHUNKS];            // per-chunk running max
__device__ float g_pl[NB * CHUNKS];            // per-chunk running sum
__device__ float g_pacc[NB * CHUNKS * ND];     // per-chunk context partials (1 MB)

// ---------------- packed f32x2 helpers ----------------
__device__ __forceinline__ unsigned long long pack_dup(float x) {
    unsigned long long r;
    asm("mov.b64 %0, {%1, %1};" : "=l"(r) : "f"(x));
    return r;
}
__device__ __forceinline__ unsigned long long fma2(unsigned long long a,
                                                   unsigned long long b,
                                                   unsigned long long c) {
    unsigned long long d;
    asm("fma.rn.f32x2 %0, %1, %2, %3;" : "=l"(d) : "l"(a), "l"(b), "l"(c));
    return d;
}
__device__ __forceinline__ unsigned long long add2(unsigned long long a,
                                                   unsigned long long b) {
    unsigned long long d;
    asm("add.rn.f32x2 %0, %1, %2;" : "=l"(d) : "l"(a), "l"(b));
    return d;
}
__device__ __forceinline__ void unpack2(unsigned long long p, float& lo, float& hi) {
    asm("mov.b64 {%0, %1}, %2;" : "=f"(lo), "=f"(hi) : "l"(p));
}

// ============ Kernel A: fused score + online-softmax + context partials ============
// Grid: NB*CHUNKS CTAs. CTA = (b, chunk of 256 T-rows). 8 warps, warp owns 32 rows.
// W_eo pre-packed in smem:
//   wpk[h][up][g][lane]: float4 = f32x2 packs (u=2up,2up+1) for d = g*128+4*lane+2h (+0,+1)
__global__ __launch_bounds__(A_THREADS, 2)
void ka_fused(const float* __restrict__ Eo, const float* __restrict__ H,
              const float* __restrict__ W_eo, const float* __restrict__ b_eo,
              const float* __restrict__ W_h, const float* __restrict__ b_h,
              const float* __restrict__ W_s, const float* __restrict__ b_s,
              float* __restrict__ scores, float* __restrict__ pm,
              float* __restrict__ pl, float* __restrict__ pacc) {
    __shared__ float4 wpk[2][5][4][32];        // 20 KB, 16B-aligned
    __shared__ float4 macc4[A_WARPS][ND / 4];  // 16 KB, 16B-aligned (float4-typed!)
    __shared__ float ht[NU];                   // H-term + biases (pre-tanh add)
    __shared__ float wsm[NU];                  // W_s
    __shared__ float sbs;                      // b_s
    __shared__ float wm[A_WARPS], wl[A_WARPS];

    int tid = threadIdx.x;
    int warp = tid >> 5, lane = tid & 31;
    int b = blockIdx.x / CHUNKS;
    int c = blockIdx.x % CHUNKS;

    // --- pack W_eo into smem ---
    for (int idx = tid; idx < 2 * 5 * 4 * 32; idx += A_THREADS) {
        int h = idx / 640;
        int rem = idx % 640;
        int up = rem / 128;
        int rem2 = rem % 128;
        int g = rem2 / 32;
        int l = rem2 % 32;
        int d0 = g * 128 + l * 4 + h * 2;
        float4 v;
        v.x = W_eo[d0 * NU + 2 * up];
        v.y = W_eo[d0 * NU + 2 * up + 1];
        v.z = W_eo[(d0 + 1) * NU + 2 * up];
        v.w = W_eo[(d0 + 1) * NU + 2 * up + 1];
        wpk[h][up][g][l] = v;
    }

    // --- hterm[u] = H[b].W_h[:,u] + b_h[u] + b_eo[u] ---
    for (int u = warp; u < NU; u += A_WARPS) {
        float p = 0.f;
        for (int d = lane; d < ND; d += 32)
            p += H[b * ND + d] * W_h[d * NU + u];
#pragma unroll
        for (int off = 16; off; off >>= 1)
            p += __shfl_xor_sync(0xffffffffu, p, off);
        if (lane == 0) ht[u] = p + b_h[u] + b_eo[u];
    }
    if (tid < NU) wsm[tid] = W_s[tid];
    if (tid == 0) sbs = b_s[0];
    __syncthreads();

    // --- per-warp online softmax + context accumulation over 32 rows ---
    float m = -1e30f, l = 0.f;
    float4 ca[4];
#pragma unroll
    for (int g = 0; g < 4; g++) ca[g] = make_float4(0.f, 0.f, 0.f, 0.f);

    long rowbase = (long)b * NT + (long)c * CROWS;

    for (int k = 0; k < ROWS_PER_WARP; k++) {
        int r = k * A_WARPS + warp;
        long row = rowbase + r;
        const float* ep = Eo + row * ND + lane * 4;

        float4 e[4];
#pragma unroll
        for (int g = 0; g < 4; g++)
            e[g] = *reinterpret_cast<const float4*>(ep + g * 128);

        // 10 dots as 5 f32x2 packs
        unsigned long long accs[5] = {0ULL, 0ULL, 0ULL, 0ULL, 0ULL};
#pragma unroll
        for (int g = 0; g < 4; g++) {
            unsigned long long d0 = pack_dup(e[g].x);
            unsigned long long d1 = pack_dup(e[g].y);
            unsigned long long d2 = pack_dup(e[g].z);
            unsigned long long d3 = pack_dup(e[g].w);
#pragma unroll
            for (int up = 0; up < 5; up++) {
                ulonglong2 wa = *reinterpret_cast<const ulonglong2*>(&wpk[0][up][g][lane]);
                ulonglong2 wb = *reinterpret_cast<const ulonglong2*>(&wpk[1][up][g][lane]);
                accs[up] = fma2(d0, wa.x, accs[up]);
                accs[up] = fma2(d1, wa.y, accs[up]);
                accs[up] = fma2(d2, wb.x, accs[up]);
                accs[up] = fma2(d3, wb.y, accs[up]);
            }
        }
        // butterfly: every lane ends with full reduced packs
#pragma unroll
        for (int off = 16; off; off >>= 1)
#pragma unroll
            for (int up = 0; up < 5; up++)
                accs[up] = add2(accs[up], __shfl_xor_sync(0xffffffffu, accs[up], off));

        // score = b_s + sum_u W_s[u] * tanh(dot_u + ht[u])   (precise exp-based tanh)
        float s = sbs;
#pragma unroll
        for (int up = 0; up < 5; up++) {
            float lo, hi;
            unpack2(accs[up], lo, hi);
            float x0 = fminf(fmaxf(lo + ht[2 * up], -15.f), 15.f);
            float x1 = fminf(fmaxf(hi + ht[2 * up + 1], -15.f), 15.f);
            float e0 = __expf(2.f * x0);
            float e1 = __expf(2.f * x1);
            s += wsm[2 * up] * __fdividef(e0 - 1.f, e0 + 1.f);
            s += wsm[2 * up + 1] * __fdividef(e1 - 1.f, e1 + 1.f);
        }

        if (lane == 0) scores[row] = s;

        // online update (warp-uniform branch; s identical across lanes)
        if (s > m) {
            float sc = __expf(m - s);   // first iter: exp(-huge) = 0
            l = l * sc + 1.f;
#pragma unroll
            for (int g = 0; g < 4; g++) {
                ca[g].x = ca[g].x * sc + e[g].x;
                ca[g].y = ca[g].y * sc + e[g].y;
                ca[g].z = ca[g].z * sc + e[g].z;
                ca[g].w = ca[g].w * sc + e[g].w;
            }
            m = s;
        } else {
            float w = __expf(s - m);
            l += w;
#pragma unroll
            for (int g = 0; g < 4; g++) {
                ca[g].x += w * e[g].x;
                ca[g].y += w * e[g].y;
                ca[g].z += w * e[g].z;
                ca[g].w += w * e[g].w;
            }
        }
    }

    // --- merge 8 warps within CTA ---
    if (lane == 0) { wm[warp] = m; wl[warp] = l; }
#pragma unroll
    for (int g = 0; g < 4; g++)
        macc4[warp][g * 32 + lane] = ca[g];
    __syncthreads();

    float mc = wm[0];
#pragma unroll
    for (int w = 1; w < A_WARPS; w++) mc = fmaxf(mc, wm[w]);
    float lc = 0.f;
#pragma unroll
    for (int w = 0; w < A_WARPS; w++) lc += wl[w] * __expf(wm[w] - mc);

    const float* maccf = reinterpret_cast<const float*>(macc4);
    for (int d = tid; d < ND; d += A_THREADS) {
        float v = 0.f;
#pragma unroll
        for (int w = 0; w < A_WARPS; w++)
            v += maccf[w * ND + d] * __expf(wm[w] - mc);
        pacc[(long)(b * CHUNKS + c) * ND + d] = v;
    }
    if (tid == 0) {
        pm[b * CHUNKS + c] = mc;
        pl[b * CHUNKS + c] = lc;
    }
}

// ============ Kernel B: merge chunks -> context + final weights ============
__global__ __launch_bounds__(256)
void kb_merge(const float* __restrict__ scores, const float* __restrict__ pm,
              const float* __restrict__ pl, const float* __restrict__ pacc,
              float* __restrict__ ctx, float* __restrict__ weight) {
    int b = blockIdx.x;
    int tid = threadIdx.x;
    __shared__ float f[CHUNKS];
    __shared__ float s_m, s_invl;

    if (tid == 0) {
        float m = pm[b * CHUNKS];
#pragma unroll
        for (int c = 1; c < CHUNKS; c++) m = fmaxf(m, pm[b * CHUNKS + c]);
        float l = 0.f;
#pragma unroll
        for (int c = 0; c < CHUNKS; c++)
            l += pl[b * CHUNKS + c] * __expf(pm[b * CHUNKS + c] - m);
        s_m = m;
        s_invl = __fdividef(1.f, l);
    }
    __syncthreads();
    float m = s_m, invl = s_invl;
    if (tid < CHUNKS) f[tid] = __expf(pm[b * CHUNKS + tid] - m) * invl;
    __syncthreads();

    for (int d = tid; d < ND; d += 256) {
        float v = 0.f;
#pragma unroll
        for (int c = 0; c < CHUNKS; c++)
            v += pacc[(long)(b * CHUNKS + c) * ND + d] * f[c];
        ctx[(long)b * ND + d] = v;
    }

    for (int t = tid; t < NT; t += 256)
        weight[(long)b * NT + t] = __expf(scores[(long)b * NT + t] - m) * invl;
}

// ================= launch =================
extern "C" void kernel_launch(void* const* d_in, const int* in_sizes, int n_in,
                              void* d_out, int out_size) {
    const float* Eo   = (const float*)d_in[0];
    const float* H    = (const float*)d_in[1];
    const float* W_eo = (const float*)d_in[2];
    const float* b_eo = (const float*)d_in[3];
    const float* W_h  = (const float*)d_in[4];
    const float* b_h  = (const float*)d_in[5];
    const float* W_s  = (const float*)d_in[6];
    const float* b_s  = (const float*)d_in[7];

    float* out    = (float*)d_out;
    float* ctx    = out;            // [B, D]
    float* weight = out + NB * ND;  // [B, T]

    float* scores; cudaGetSymbolAddress((void**)&scores, g_scores);
    float* pm;     cudaGetSymbolAddress((void**)&pm, g_pm);
    float* pl;     cudaGetSymbolAddress((void**)&pl, g_pl);
    float* pacc;   cudaGetSymbolAddress((void**)&pacc, g_pacc);

    ka_fused<<<NB * CHUNKS, A_THREADS>>>(Eo, H, W_eo, b_eo, W_h, b_h, W_s, b_s,
                                         scores, pm, pl, pacc);
    kb_merge<<<NB, 256>>>(scores, pm, pl, pacc, ctx, weight);
}